// round 14
// baseline (speedup 1.0000x reference)
#include <cuda_runtime.h>

#define Bn 4
#define Cn 256
#define ICn 128
#define Sn 64
#define NTOK (Bn*Sn)        // 256
#define REGION 1024
#define EPSf 1e-5f

// single-launch layout: pool blocks, then projattn blocks (bid-ordered)
#define POOL_BLKS  8192
#define GEMM_BASE  POOL_BLKS                // 96 GEMM tile blocks
#define FOLD_BASE  (GEMM_BASE + 96)         // 8 BN-fold blocks
#define ATTN_BASE  (FOLD_BASE + 8)          // 256 attention blocks
#define TOTAL_BLKS (ATTN_BASE + 256)        // 8552
#define PROJ_CNT   104                      // 96 GEMM + 8 fold

// Scratch (allocation-free __device__ globals)
__device__ float d_P   [NTOK*Cn];      // pooled tokens [tok][c]
__device__ float d_g   [NTOK*ICn];
__device__ float d_th  [NTOK*ICn];
__device__ float d_ph  [NTOK*ICn];
__device__ float d_Wt  [ICn*Cn];       // BN-folded W transposed: [i][c]
__device__ float d_bias[Cn];           // BN-folded bias
__device__ float d_val [Bn*Cn*Sn];     // broadcast values [b][c][s]

// stage counters (reset by last attn block each run; launches are stream-serial)
__device__ unsigned c_pool  = 0;
__device__ unsigned c_proj  = 0;
__device__ unsigned c_attn  = 0;

// ---------------------------------------------------------------------------
// K1: pool (blocks 0..8191) + projections (8192..8287) + BN fold (8288..8295)
//     + attention (8296..8551), ordered by blockIdx so later stages only
//     become resident as earlier ones drain.
// ---------------------------------------------------------------------------
__global__ void pool_projattn_kernel(
        const float* __restrict__ x,
        const float* __restrict__ g_w,  const float* __restrict__ g_b,
        const float* __restrict__ th_w, const float* __restrict__ th_b,
        const float* __restrict__ ph_w, const float* __restrict__ ph_b,
        const float* __restrict__ W_w,  const float* __restrict__ W_b,
        const float* __restrict__ gamma,const float* __restrict__ beta,
        const float* __restrict__ mean, const float* __restrict__ var) {
    int bid = blockIdx.x;
    int tid = threadIdx.x;

    // ======================= G0: stripe mean pool =======================
    if (bid < POOL_BLKS) {
        int warp = (bid * 256 + tid) >> 5;         // 0..65535
        int lane = tid & 31;
        const float4* p = (const float4*)(x + (size_t)warp * REGION);
        float sum = 0.f;
#pragma unroll
        for (int i = 0; i < 8; i++) {
            float4 v = __ldcs(p + lane + i * 32);
            sum += (v.x + v.y) + (v.z + v.w);
        }
#pragma unroll
        for (int o = 16; o; o >>= 1) sum += __shfl_down_sync(0xffffffffu, sum, o);
        if (lane == 0) {
            int b   = warp >> 14;
            int rem = warp & 16383;
            int c   = rem >> 6;
            int s   = rem & 63;
            d_P[(b * Sn + s) * Cn + c] = sum * (1.0f / REGION);
        }
        __syncthreads();
        if (tid == 0) { __threadfence(); atomicAdd(&c_pool, 1u); }
        return;
    }

    // ================= G1a: proj GEMM (needs all of d_P) =================
    if (bid < FOLD_BASE) {
        if (tid == 0) {
            while (*(volatile unsigned*)&c_pool < POOL_BLKS) __nanosleep(32);
            __threadfence();
        }
        __syncthreads();

        __shared__ float As[32][33];
        __shared__ float Bs[32][33];
        int local = bid - GEMM_BASE;         // 0..95
        int t0 = (local & 7) * 32;
        int oT = local >> 3;                 // 0..11
        int mat  = oT >> 2;
        int row0 = (oT & 3) * 32;
        const float* wsrc = (mat == 0) ? g_w : (mat == 1) ? th_w : ph_w;
        const float* bsrc = (mat == 0) ? g_b : (mat == 1) ? th_b : ph_b;
        float*       osrc = (mat == 0) ? d_g : (mat == 1) ? d_th : d_ph;

        int tx = tid & 15, ty = tid >> 4;
        float acc[2][2] = {{0.f,0.f},{0.f,0.f}};

        for (int k0 = 0; k0 < Cn; k0 += 32) {
#pragma unroll
            for (int l = 0; l < 4; l++) {
                int idx = tid + l * 256;
                int r = idx >> 5, k = idx & 31;
                As[r][k] = d_P[(t0 + r) * Cn + k0 + k];
                Bs[r][k] = wsrc[(row0 + r) * Cn + k0 + k];
            }
            __syncthreads();
#pragma unroll
            for (int k = 0; k < 32; k++) {
                float a0 = As[ty * 2][k], a1 = As[ty * 2 + 1][k];
                float b0 = Bs[tx * 2][k], b1 = Bs[tx * 2 + 1][k];
                acc[0][0] = fmaf(a0, b0, acc[0][0]);
                acc[0][1] = fmaf(a0, b1, acc[0][1]);
                acc[1][0] = fmaf(a1, b0, acc[1][0]);
                acc[1][1] = fmaf(a1, b1, acc[1][1]);
            }
            __syncthreads();
        }
#pragma unroll
        for (int di = 0; di < 2; di++)
#pragma unroll
            for (int dj = 0; dj < 2; dj++) {
                int tok = t0 + ty * 2 + di;
                int i   = row0 + tx * 2 + dj;
                osrc[tok * ICn + i] = acc[di][dj] + bsrc[i];
            }
        __syncthreads();
        if (tid == 0) { __threadfence(); atomicAdd(&c_proj, 1u); }
        return;
    }

    // ========= G1b: BN fold of W (no pool dependency, runs early) =========
    if (bid < ATTN_BASE) {
        int base = (bid - FOLD_BASE) * 4096;
#pragma unroll
        for (int l = 0; l < 16; l++) {
            int idx = base + l * 256 + tid;      // over [c][i]
            int c = idx >> 7, i = idx & 127;
            float inv = gamma[c] * rsqrtf(var[c] + EPSf);
            d_Wt[i * Cn + c] = W_w[idx] * inv;
        }
        if (bid == FOLD_BASE) {
            int c = tid;
            float inv = gamma[c] * rsqrtf(var[c] + EPSf);
            d_bias[c] = (W_b[c] - mean[c]) * inv + beta[c];
        }
        __syncthreads();
        if (tid == 0) { __threadfence(); atomicAdd(&c_proj, 1u); }
        return;
    }

    // ================= G2: attention (waits on proj+fold) =================
    if (tid == 0) {
        while (*(volatile unsigned*)&c_proj < PROJ_CNT) __nanosleep(32);
        __threadfence();
    }
    __syncthreads();

    __shared__ float th_s[ICn];
    __shared__ float at_s[Sn];
    __shared__ float y_s[ICn];
    int bs = bid - ATTN_BASE;            // b*Sn + s
    int b  = bs >> 6;
    int s  = bs & 63;
    int warp = tid >> 5, lane = tid & 31;

    if (tid < ICn) th_s[tid] = d_th[bs * ICn + tid];
    __syncthreads();

    // f[r]: 8 warps x 8 dots; preload all 8 ph vectors (MLP 8), then reduce
    {
        const float4* th4 = (const float4*)th_s;
        float4 a = th4[lane];
        float4 ph_r[8];
#pragma unroll
        for (int d = 0; d < 8; d++) {
            int r = warp * 8 + d;
            ph_r[d] = ((const float4*)(d_ph + (b * Sn + r) * ICn))[lane];
        }
#pragma unroll
        for (int d = 0; d < 8; d++) {
            float acc = a.x * ph_r[d].x + a.y * ph_r[d].y
                      + a.z * ph_r[d].z + a.w * ph_r[d].w;
#pragma unroll
            for (int o = 16; o; o >>= 1) acc += __shfl_down_sync(0xffffffffu, acc, o);
            if (lane == 0) at_s[warp * 8 + d] = acc;
        }
    }
    __syncthreads();

    // softmax over 64 entries by warp 0
    if (warp == 0) {
        float v0 = at_s[lane], v1 = at_s[lane + 32];
        float m = fmaxf(v0, v1);
#pragma unroll
        for (int o = 16; o; o >>= 1) m = fmaxf(m, __shfl_xor_sync(0xffffffffu, m, o));
        float e0 = __expf(v0 - m), e1 = __expf(v1 - m);
        float sum = e0 + e1;
#pragma unroll
        for (int o = 16; o; o >>= 1) sum += __shfl_xor_sync(0xffffffffu, sum, o);
        float inv = 1.0f / sum;
        at_s[lane]      = e0 * inv;
        at_s[lane + 32] = e1 * inv;
    }
    __syncthreads();

    // y[i] = sum_r attn[r] * g[r][i]; 128 threads, 4-way split accumulators
    if (tid < ICn) {
        const float* gb = d_g + b * Sn * ICn + tid;
        float a0 = 0.f, a1 = 0.f, a2 = 0.f, a3 = 0.f;
#pragma unroll
        for (int r = 0; r < Sn; r += 4) {
            a0 = fmaf(at_s[r],     gb[(r)     * ICn], a0);
            a1 = fmaf(at_s[r + 1], gb[(r + 1) * ICn], a1);
            a2 = fmaf(at_s[r + 2], gb[(r + 2) * ICn], a2);
            a3 = fmaf(at_s[r + 3], gb[(r + 3) * ICn], a3);
        }
        y_s[tid] = (a0 + a1) + (a2 + a3);
    }
    __syncthreads();

    // val[b][c][s] = Wt[:,c] . y + bias[c]; 256 threads, 4-way accumulators
    {
        const float* wt = d_Wt + tid;    // stride Cn per i, coalesced over c
        float a0 = 0.f, a1 = 0.f, a2 = 0.f, a3 = 0.f;
#pragma unroll
        for (int i = 0; i < ICn; i += 4) {
            a0 = fmaf(y_s[i],     wt[(i)     * Cn], a0);
            a1 = fmaf(y_s[i + 1], wt[(i + 1) * Cn], a1);
            a2 = fmaf(y_s[i + 2], wt[(i + 2) * Cn], a2);
            a3 = fmaf(y_s[i + 3], wt[(i + 3) * Cn], a3);
        }
        d_val[(b * Cn + tid) * Sn + s] = (a0 + a1) + (a2 + a3) + d_bias[tid];
    }

    // last attn block resets all counters for the next graph replay
    __syncthreads();
    if (tid == 0) {
        __threadfence();
        if (atomicAdd(&c_attn, 1u) == 255u) {
            c_pool = 0; c_proj = 0; c_attn = 0;
            __threadfence();
        }
    }
}

// ---------------------------------------------------------------------------
// K2: broadcast + residual. 2 independent float4 per thread (R11 shape).
// ---------------------------------------------------------------------------
__global__ void residual_kernel(const float* __restrict__ x, float* __restrict__ z) {
    const int STRIDE = 32768 * 256;                 // float4 stride (half total)
    int t = blockIdx.x * 256 + threadIdx.x;

    int i0 = t, i1 = t + STRIDE;
    float v0 = d_val[i0 >> 8];
    float v1 = d_val[i1 >> 8];
    float4 a0 = __ldcs((const float4*)x + i0);
    float4 a1 = __ldcs((const float4*)x + i1);
    a0.x += v0; a0.y += v0; a0.z += v0; a0.w += v0;
    a1.x += v1; a1.y += v1; a1.z += v1; a1.w += v1;
    __stcs((float4*)z + i0, a0);
    __stcs((float4*)z + i1, a1);
}

// ---------------------------------------------------------------------------
extern "C" void kernel_launch(void* const* d_in, const int* in_sizes, int n_in,
                              void* d_out, int out_size) {
    const float* x      = (const float*)d_in[0];
    const float* g_w    = (const float*)d_in[1];
    const float* g_b    = (const float*)d_in[2];
    const float* th_w   = (const float*)d_in[3];
    const float* th_b   = (const float*)d_in[4];
    const float* ph_w   = (const float*)d_in[5];
    const float* ph_b   = (const float*)d_in[6];
    const float* W_w    = (const float*)d_in[7];
    const float* W_b    = (const float*)d_in[8];
    const float* gamma  = (const float*)d_in[9];
    const float* beta   = (const float*)d_in[10];
    const float* mean   = (const float*)d_in[11];
    const float* var    = (const float*)d_in[12];
    float* z = (float*)d_out;

    pool_projattn_kernel<<<TOTAL_BLKS, 256>>>(x, g_w, g_b, th_w, th_b, ph_w, ph_b,
                                              W_w, W_b, gamma, beta, mean, var);
    residual_kernel<<<32768, 256>>>(x, z);
}

// round 15
// speedup vs baseline: 1.0905x; 1.0905x over previous
#include <cuda_runtime.h>

#define Bn 4
#define Cn 256
#define ICn 128
#define Sn 64
#define NTOK (Bn*Sn)        // 256
#define REGION 1024
#define EPSf 1e-5f

// projattn block-group layout (single launch, all blocks co-resident)
#define PROJ_BLKS 104       // 96 GEMM tiles + 8 BN-fold
#define ATTN_BLKS 256
#define PA_TOTAL  (PROJ_BLKS + ATTN_BLKS)   // 360 < resident capacity

// Scratch (allocation-free __device__ globals)
__device__ float d_P   [NTOK*Cn];      // pooled tokens [tok][c]
__device__ float d_g   [NTOK*ICn];
__device__ float d_th  [NTOK*ICn];
__device__ float d_ph  [NTOK*ICn];
__device__ float d_Wt  [ICn*Cn];       // BN-folded W transposed: [i][c]
__device__ float d_bias[Cn];           // BN-folded bias
__device__ float d_val [Bn*Cn*Sn];     // broadcast values [b][c][s]

// intra-kernel stage counters (reset by last attn block; stream-serial safe)
__device__ unsigned pc_done = 0;
__device__ unsigned ac_done = 0;

// ---------------------------------------------------------------------------
// K1: stripe mean pool. One warp per 1024-float contiguous region (R11 shape).
// ---------------------------------------------------------------------------
__global__ void pool_kernel(const float* __restrict__ x) {
    int warp = (blockIdx.x * blockDim.x + threadIdx.x) >> 5;   // 0..65535
    int lane = threadIdx.x & 31;
    const float4* p = (const float4*)(x + (size_t)warp * REGION);
    float sum = 0.f;
#pragma unroll
    for (int i = 0; i < 8; i++) {
        float4 v = __ldcs(p + lane + i * 32);
        sum += (v.x + v.y) + (v.z + v.w);
    }
#pragma unroll
    for (int o = 16; o; o >>= 1) sum += __shfl_down_sync(0xffffffffu, sum, o);
    if (lane == 0) {
        int b   = warp >> 14;
        int rem = warp & 16383;
        int c   = rem >> 6;
        int s   = rem & 63;
        d_P[(b * Sn + s) * Cn + c] = sum * (1.0f / REGION);
    }
}

// ---------------------------------------------------------------------------
// K2: fused projections (+BN fold) and attention in ONE kernel.
// Blocks 0..95: g/th/ph GEMM, 2 k-stages of K=128 (deep-MLP smem staging).
// Blocks 96..103: BN fold of W. Blocks 104..359: attention rows.
// ---------------------------------------------------------------------------
__global__ void projattn_kernel(
        const float* __restrict__ g_w,  const float* __restrict__ g_b,
        const float* __restrict__ th_w, const float* __restrict__ th_b,
        const float* __restrict__ ph_w, const float* __restrict__ ph_b,
        const float* __restrict__ W_w,  const float* __restrict__ W_b,
        const float* __restrict__ gamma,const float* __restrict__ beta,
        const float* __restrict__ mean, const float* __restrict__ var) {
    int bid = blockIdx.x;
    int tid = threadIdx.x;

    if (bid < 96) {
        // ---- tiled GEMM: 32 tokens x 32 outputs, K=256 in 2 stages of 128 ----
        __shared__ float As[32 * 129];   // [row][k], stride 129 (conflict-free)
        __shared__ float Bs[32 * 129];
        int t0 = (bid & 7) * 32;
        int oT = bid >> 3;                   // 0..11
        int mat  = oT >> 2;
        int row0 = (oT & 3) * 32;
        const float* wsrc = (mat == 0) ? g_w : (mat == 1) ? th_w : ph_w;
        const float* bsrc = (mat == 0) ? g_b : (mat == 1) ? th_b : ph_b;
        float*       osrc = (mat == 0) ? d_g : (mat == 1) ? d_th : d_ph;

        int tx = tid & 15, ty = tid >> 4;
        float acc[2][2] = {{0.f,0.f},{0.f,0.f}};

#pragma unroll
        for (int stage = 0; stage < 2; stage++) {
            int k0 = stage * 128;
            // load 32x128 of P and W: 1024 float4 each, 4 per thread, MLP 8
#pragma unroll
            for (int l = 0; l < 4; l++) {
                int q  = tid + l * 256;          // float4 index 0..1023
                int r  = q >> 5;                 // row 0..31
                int k4 = q & 31;                 // float4 within row
                float4 av = *(const float4*)(d_P  + (t0 + r) * Cn + k0 + k4 * 4);
                float4 bv = *(const float4*)(wsrc + (row0 + r) * Cn + k0 + k4 * 4);
                float* ad = As + r * 129 + k4 * 4;
                float* bd = Bs + r * 129 + k4 * 4;
                ad[0] = av.x; ad[1] = av.y; ad[2] = av.z; ad[3] = av.w;
                bd[0] = bv.x; bd[1] = bv.y; bd[2] = bv.z; bd[3] = bv.w;
            }
            __syncthreads();
            const float* a0p = As + (ty * 2) * 129;
            const float* a1p = As + (ty * 2 + 1) * 129;
            const float* b0p = Bs + (tx * 2) * 129;
            const float* b1p = Bs + (tx * 2 + 1) * 129;
#pragma unroll 4
            for (int k = 0; k < 128; k++) {
                float a0 = a0p[k], a1 = a1p[k];
                float b0 = b0p[k], b1 = b1p[k];
                acc[0][0] = fmaf(a0, b0, acc[0][0]);
                acc[0][1] = fmaf(a0, b1, acc[0][1]);
                acc[1][0] = fmaf(a1, b0, acc[1][0]);
                acc[1][1] = fmaf(a1, b1, acc[1][1]);
            }
            __syncthreads();
        }
#pragma unroll
        for (int di = 0; di < 2; di++)
#pragma unroll
            for (int dj = 0; dj < 2; dj++) {
                int tok = t0 + ty * 2 + di;
                int i   = row0 + tx * 2 + dj;
                osrc[tok * ICn + i] = acc[di][dj] + bsrc[i];
            }
        __syncthreads();
        if (tid == 0) { __threadfence(); atomicAdd(&pc_done, 1u); }
        return;
    }

    if (bid < PROJ_BLKS) {
        // ---- BN fold + transpose of W: 8 blocks x 256 threads x 16 elems ----
        int base = (bid - 96) * 4096;
#pragma unroll
        for (int l = 0; l < 16; l++) {
            int idx = base + l * 256 + tid;      // over [c][i]
            int c = idx >> 7, i = idx & 127;
            float inv = gamma[c] * rsqrtf(var[c] + EPSf);
            d_Wt[i * Cn + c] = W_w[idx] * inv;
        }
        if (bid == 96) {
            int c = tid;
            float inv = gamma[c] * rsqrtf(var[c] + EPSf);
            d_bias[c] = (W_b[c] - mean[c]) * inv + beta[c];
        }
        __syncthreads();
        if (tid == 0) { __threadfence(); atomicAdd(&pc_done, 1u); }
        return;
    }

    // ================= attention blocks: wait for proj =================
    if (tid == 0) {
        while (*(volatile unsigned*)&pc_done < PROJ_BLKS) __nanosleep(32);
        __threadfence();
    }
    __syncthreads();

    __shared__ float th_s[ICn];
    __shared__ float at_s[Sn];
    __shared__ float y_s[ICn];
    int bs = bid - PROJ_BLKS;            // b*Sn + s
    int b  = bs >> 6;
    int s  = bs & 63;
    int warp = tid >> 5, lane = tid & 31;

    if (tid < ICn) th_s[tid] = d_th[bs * ICn + tid];
    __syncthreads();

    // f[r]: 8 warps x 8 dots; preload all 8 ph vectors (MLP 8), then reduce
    {
        const float4* th4 = (const float4*)th_s;
        float4 a = th4[lane];
        float4 ph_r[8];
#pragma unroll
        for (int d = 0; d < 8; d++) {
            int r = warp * 8 + d;
            ph_r[d] = ((const float4*)(d_ph + (b * Sn + r) * ICn))[lane];
        }
#pragma unroll
        for (int d = 0; d < 8; d++) {
            float acc = a.x * ph_r[d].x + a.y * ph_r[d].y
                      + a.z * ph_r[d].z + a.w * ph_r[d].w;
#pragma unroll
            for (int o = 16; o; o >>= 1) acc += __shfl_down_sync(0xffffffffu, acc, o);
            if (lane == 0) at_s[warp * 8 + d] = acc;
        }
    }
    __syncthreads();

    // softmax over 64 entries by warp 0
    if (warp == 0) {
        float v0 = at_s[lane], v1 = at_s[lane + 32];
        float m = fmaxf(v0, v1);
#pragma unroll
        for (int o = 16; o; o >>= 1) m = fmaxf(m, __shfl_xor_sync(0xffffffffu, m, o));
        float e0 = __expf(v0 - m), e1 = __expf(v1 - m);
        float sum = e0 + e1;
#pragma unroll
        for (int o = 16; o; o >>= 1) sum += __shfl_xor_sync(0xffffffffu, sum, o);
        float inv = 1.0f / sum;
        at_s[lane]      = e0 * inv;
        at_s[lane + 32] = e1 * inv;
    }
    __syncthreads();

    // y[i] = sum_r attn[r] * g[r][i]; 128 threads, 4-way split accumulators
    if (tid < ICn) {
        const float* gb = d_g + b * Sn * ICn + tid;
        float a0 = 0.f, a1 = 0.f, a2 = 0.f, a3 = 0.f;
#pragma unroll
        for (int r = 0; r < Sn; r += 4) {
            a0 = fmaf(at_s[r],     gb[(r)     * ICn], a0);
            a1 = fmaf(at_s[r + 1], gb[(r + 1) * ICn], a1);
            a2 = fmaf(at_s[r + 2], gb[(r + 2) * ICn], a2);
            a3 = fmaf(at_s[r + 3], gb[(r + 3) * ICn], a3);
        }
        y_s[tid] = (a0 + a1) + (a2 + a3);
    }
    __syncthreads();

    // val[b][c][s] = Wt[:,c] . y + bias[c]; 256 threads, 4-way accumulators
    {
        const float* wt = d_Wt + tid;    // stride Cn per i, coalesced over c
        float a0 = 0.f, a1 = 0.f, a2 = 0.f, a3 = 0.f;
#pragma unroll
        for (int i = 0; i < ICn; i += 4) {
            a0 = fmaf(y_s[i],     wt[(i)     * Cn], a0);
            a1 = fmaf(y_s[i + 1], wt[(i + 1) * Cn], a1);
            a2 = fmaf(y_s[i + 2], wt[(i + 2) * Cn], a2);
            a3 = fmaf(y_s[i + 3], wt[(i + 3) * Cn], a3);
        }
        d_val[(b * Cn + tid) * Sn + s] = (a0 + a1) + (a2 + a3) + d_bias[tid];
    }

    // last attn block resets counters for the next graph replay
    __syncthreads();
    if (tid == 0) {
        __threadfence();
        if (atomicAdd(&ac_done, 1u) == ATTN_BLKS - 1) {
            pc_done = 0; ac_done = 0;
            __threadfence();
        }
    }
}

// ---------------------------------------------------------------------------
// K3: broadcast + residual. 2 independent float4 per thread (R11 shape).
// ---------------------------------------------------------------------------
__global__ void residual_kernel(const float* __restrict__ x, float* __restrict__ z) {
    const int STRIDE = 32768 * 256;                 // float4 stride (half total)
    int t = blockIdx.x * 256 + threadIdx.x;

    int i0 = t, i1 = t + STRIDE;
    float v0 = d_val[i0 >> 8];
    float v1 = d_val[i1 >> 8];
    float4 a0 = __ldcs((const float4*)x + i0);
    float4 a1 = __ldcs((const float4*)x + i1);
    a0.x += v0; a0.y += v0; a0.z += v0; a0.w += v0;
    a1.x += v1; a1.y += v1; a1.z += v1; a1.w += v1;
    __stcs((float4*)z + i0, a0);
    __stcs((float4*)z + i1, a1);
}

// ---------------------------------------------------------------------------
extern "C" void kernel_launch(void* const* d_in, const int* in_sizes, int n_in,
                              void* d_out, int out_size) {
    const float* x      = (const float*)d_in[0];
    const float* g_w    = (const float*)d_in[1];
    const float* g_b    = (const float*)d_in[2];
    const float* th_w   = (const float*)d_in[3];
    const float* th_b   = (const float*)d_in[4];
    const float* ph_w   = (const float*)d_in[5];
    const float* ph_b   = (const float*)d_in[6];
    const float* W_w    = (const float*)d_in[7];
    const float* W_b    = (const float*)d_in[8];
    const float* gamma  = (const float*)d_in[9];
    const float* beta   = (const float*)d_in[10];
    const float* mean   = (const float*)d_in[11];
    const float* var    = (const float*)d_in[12];
    float* z = (float*)d_out;

    pool_kernel<<<8192, 256>>>(x);
    projattn_kernel<<<PA_TOTAL, 256>>>(g_w, g_b, th_w, th_b, ph_w, ph_b,
                                       W_w, W_b, gamma, beta, mean, var);
    residual_kernel<<<32768, 256>>>(x, z);
}